// round 9
// baseline (speedup 1.0000x reference)
#include <cuda_runtime.h>
#include <math.h>
#include <float.h>

// ---------------- problem constants ----------------
#define F_DIM 2048
#define H_DIM 256
#define C_DIM 64
#define K_DIM 16
#define TOPK  10
#define N_MAX 65536
#define EPS   1e-6f
#define R_TOT (TOPK + C_DIM)     // 74 embedding rows
#define PADW  257                // padded row width for k4 smem

#define ROWS_PB 32                                  // rows per k1 block (1 row/warp)
#define NB2_MAX ((N_MAX + 1023) / 1024)             // k2a blocks total (64)

// f-embedding chunking: 10 rows share W2 loads, 64 K-chunks of 32
#define KCHF  64
#define KCSZF (F_DIM / KCHF)     // 32
// proto-embedding chunking: 8 rows/group, 32 K-chunks of 64
#define RGP   8
#define KCHP  32
#define KCSZP (F_DIM / KCHP)     // 64

// ---------------- device scratch ----------------
__device__ unsigned long long g_keys[N_MAX];
__device__ unsigned long long g_cand[NB2_MAX * TOPK];
__device__ int   g_topidx[TOPK];
__device__ float g_part_f[TOPK * KCHF * H_DIM];
__device__ float g_part_p[C_DIM * KCHP * H_DIM];
__device__ float g_fp[R_TOT * H_DIM];   // rows 0..9 = f, 10..73 = p

// ---------------- key packing: larger key = better (higher score, then lower idx) ----------------
__device__ __forceinline__ unsigned long long make_key(float v, int idx) {
    unsigned int u = __float_as_uint(v);
    u = (u & 0x80000000u) ? ~u : (u | 0x80000000u);     // order-preserving float->uint
    return ((unsigned long long)u << 32) | (unsigned long long)(0x7fffffffu - (unsigned)idx);
}
__device__ __forceinline__ int key_idx(unsigned long long k) {
    return (int)(0x7fffffffu - (unsigned)(k & 0xffffffffu));
}

// warp bitonic sort of 32 u64 keys (descending; lane 0 ends with max)
__device__ __forceinline__ unsigned long long bitonic32(unsigned long long v, int lane) {
#pragma unroll
    for (int k = 2; k <= 32; k <<= 1) {
#pragma unroll
        for (int j = k >> 1; j > 0; j >>= 1) {
            unsigned long long o = __shfl_xor_sync(0xffffffffu, v, j);
            bool keepMax = (((lane & k) == 0) == ((lane & j) == 0));
            unsigned long long mx = v > o ? v : o;
            unsigned long long mn = v > o ? o : v;
            v = keepMax ? mx : mn;
        }
    }
    return v;
}

// warp-wide top-10 extraction over per-lane sorted lists (desc, 0-padded)
template <int L>
__device__ __forceinline__ void warp_top10(unsigned long long* arr, unsigned long long* out) {
#pragma unroll
    for (int it = 0; it < TOPK; it++) {
        unsigned long long m = arr[0];
#pragma unroll
        for (int off = 16; off; off >>= 1) {
            unsigned long long o = __shfl_xor_sync(0xffffffffu, m, off);
            if (o > m) m = o;
        }
        out[it] = m;
        if (arr[0] == m) {
#pragma unroll
            for (int i = 0; i < L - 1; i++) arr[i] = arr[i + 1];
            arr[L - 1] = 0ULL;
        }
    }
}

// ---------------- K1: order keys = pack(x . w_diff, row) over [base, base+rows) ----------------
// 1024 threads = 32 warps, 1 row per warp (R6-proven streaming shape).
__global__ void __launch_bounds__(1024) k1_scores(const float* __restrict__ x,
                                                  const float* __restrict__ W3,
                                                  int base, int N) {
    __shared__ float ws[F_DIM];
    int tid = threadIdx.x;
    // stage w_diff: thread t -> diffs 2t, 2t+1 from W3 float4 t
    const float4* w34 = reinterpret_cast<const float4*>(W3);   // 1024 float4
    float4 wv4 = w34[tid];
    ws[2 * tid + 0] = wv4.y - wv4.x;
    ws[2 * tid + 1] = wv4.w - wv4.z;
    __syncthreads();

    int warp = tid >> 5;
    int lane = tid & 31;
    int row  = base + blockIdx.x * ROWS_PB + warp;
    if (row >= N) return;

    const float4* ws4 = reinterpret_cast<const float4*>(ws);
    const float4* xr  = reinterpret_cast<const float4*>(x + (size_t)row * F_DIM);
    float acc = 0.f;
#pragma unroll
    for (int it = 0; it < 16; it++) {
        float4 xv = xr[lane + it * 32];        // plain LDG (test vs __ldcs)
        float4 wv = ws4[lane + it * 32];
        acc = fmaf(xv.x, wv.x, acc);
        acc = fmaf(xv.y, wv.y, acc);
        acc = fmaf(xv.z, wv.z, acc);
        acc = fmaf(xv.w, wv.w, acc);
    }
#pragma unroll
    for (int o = 16; o; o >>= 1) acc += __shfl_down_sync(0xffffffffu, acc, o);
    if (lane == 0) g_keys[row] = make_key(acc, row);
}

// ---------------- K2a: per-1024-chunk top-10 via warp bitonic ----------------
// keyBase: starting key index; candBase: starting candidate block index.
__global__ void __launch_bounds__(1024) k2a_topk(int keyBase, int candBase, int N) {
    __shared__ unsigned long long w_sm[32 * TOPK];
    int tid  = threadIdx.x;
    int warp = tid >> 5;
    int lane = tid & 31;
    int idx  = keyBase + blockIdx.x * 1024 + tid;

    unsigned long long key = (idx < N) ? g_keys[idx] : 0ULL;
    key = bitonic32(key, lane);
    if (lane < TOPK) w_sm[warp * TOPK + lane] = key;
    __syncthreads();

    if (warp == 0) {
        unsigned long long lst[TOPK];
#pragma unroll
        for (int j = 0; j < TOPK; j++) lst[j] = w_sm[lane * TOPK + j];
        unsigned long long out[TOPK];
        warp_top10<TOPK>(lst, out);
        if (lane == 0) {
#pragma unroll
            for (int j = 0; j < TOPK; j++)
                g_cand[(size_t)(candBase + blockIdx.x) * TOPK + j] = out[j];
        }
    }
}

// ---------------- K2b: merge <=640 candidates -> global top-10 ----------------
__global__ void __launch_bounds__(640) k2b_topk(int nc) {
    __shared__ unsigned long long w_sm[20 * TOPK];
    int tid  = threadIdx.x;
    int warp = tid >> 5;
    int lane = tid & 31;

    unsigned long long key = (tid < nc) ? g_cand[tid] : 0ULL;
    key = bitonic32(key, lane);
    if (lane < TOPK) w_sm[warp * TOPK + lane] = key;
    __syncthreads();

    if (warp == 0) {
        unsigned long long lst[TOPK];
#pragma unroll
        for (int j = 0; j < TOPK; j++) lst[j] = (lane < 20) ? w_sm[lane * TOPK + j] : 0ULL;
        unsigned long long out[TOPK];
        warp_top10<TOPK>(lst, out);
        if (lane == 0) {
#pragma unroll
            for (int j = 0; j < TOPK; j++) g_topidx[j] = key_idx(out[j]);
        }
    }
}

// ---------------- K3 (f rows): 10 gathered rows @ W2, grid (1, KCHF) ----------------
__global__ void __launch_bounds__(256) k3a_f(const float* __restrict__ x,
                                             const float* __restrict__ W2) {
    __shared__ float xs[TOPK][KCSZF];
    int t  = threadIdx.x;
    int kc = blockIdx.y;
    int kbase = kc * KCSZF;

    for (int i = t; i < TOPK * KCSZF; i += 256) {
        int r = i / KCSZF, c = i % KCSZF;
        xs[r][c] = x[(size_t)g_topidx[r] * F_DIM + kbase + c];
    }
    __syncthreads();

    float acc[TOPK];
#pragma unroll
    for (int i = 0; i < TOPK; i++) acc[i] = 0.f;

#pragma unroll
    for (int k0 = 0; k0 < KCSZF; k0 += 8) {
        float w[8];
#pragma unroll
        for (int u = 0; u < 8; u++)
            w[u] = W2[(size_t)(kbase + k0 + u) * H_DIM + t];
#pragma unroll
        for (int u = 0; u < 8; u++)
#pragma unroll
            for (int i = 0; i < TOPK; i++)
                acc[i] = fmaf(xs[i][k0 + u], w[u], acc[i]);
    }

#pragma unroll
    for (int i = 0; i < TOPK; i++)
        g_part_f[((size_t)i * KCHF + kc) * H_DIM + t] = acc[i];
}

__global__ void __launch_bounds__(256) k3b_f(const float* __restrict__ b2) {
    int r = blockIdx.x;
    int t = threadIdx.x;
    float s = b2[t];
#pragma unroll 8
    for (int c = 0; c < KCHF; c++) s += g_part_f[((size_t)r * KCHF + c) * H_DIM + t];
    g_fp[r * H_DIM + t] = s;
}

// ---------------- K3 (proto rows): side stream ----------------
__global__ void __launch_bounds__(256) k3a_p(const float* __restrict__ proto,
                                             const float* __restrict__ W2) {
    __shared__ float xs[RGP][KCSZP];
    int t  = threadIdx.x;
    int rg = blockIdx.x;
    int kc = blockIdx.y;
    int kbase = kc * KCSZP;

    for (int i = t; i < RGP * KCSZP; i += 256) {
        int r = i >> 6, c = i & 63;
        xs[r][c] = proto[(size_t)(rg * RGP + r) * F_DIM + kbase + c];
    }
    __syncthreads();

    float acc[RGP];
#pragma unroll
    for (int i = 0; i < RGP; i++) acc[i] = 0.f;

    for (int k0 = 0; k0 < KCSZP; k0 += 8) {
        float w[8];
#pragma unroll
        for (int u = 0; u < 8; u++)
            w[u] = W2[(size_t)(kbase + k0 + u) * H_DIM + t];
#pragma unroll
        for (int u = 0; u < 8; u++)
#pragma unroll
            for (int i = 0; i < RGP; i++)
                acc[i] = fmaf(xs[i][k0 + u], w[u], acc[i]);
    }

#pragma unroll
    for (int i = 0; i < RGP; i++)
        g_part_p[((size_t)(rg * RGP + i) * KCHP + kc) * H_DIM + t] = acc[i];
}

__global__ void __launch_bounds__(256) k3b_p(const float* __restrict__ b2) {
    int r = blockIdx.x;
    int t = threadIdx.x;
    float s = b2[t];
#pragma unroll 8
    for (int c = 0; c < KCHP; c++) s += g_part_p[((size_t)r * KCHP + c) * H_DIM + t];
    g_fp[(TOPK + r) * H_DIM + t] = s;
}

// ---------------- K4: similarity + normalize + mean + head ----------------
__global__ void __launch_bounds__(640) k4_head(const float* __restrict__ Wrho,
                                               const float* __restrict__ brho,
                                               const float* __restrict__ Wc,
                                               const float* __restrict__ bc,
                                               float* __restrict__ out,
                                               int out_size) {
    extern __shared__ float rows[];          // R_TOT * PADW floats
    __shared__ float sim[TOPK][C_DIM];
    __shared__ float rowmax[TOPK];
    __shared__ float coding[C_DIM];
    __shared__ float hidden[K_DIM];
    __shared__ float logits[2];
    int t = threadIdx.x;

    for (int i = t; i < R_TOT * H_DIM; i += 640) {
        int r = i >> 8;
        int h = i & 255;
        float v = g_fp[i];
        if (r >= TOPK) v -= EPS;             // fold +EPS into prototype rows
        rows[r * PADW + h] = v;
    }
    __syncthreads();

    {
        int r = t / C_DIM;
        int c = t % C_DIM;
        const float* f = rows + r * PADW;
        const float* q = rows + (TOPK + c) * PADW;
        float s0 = 0.f, s1 = 0.f, s2 = 0.f, s3 = 0.f;
#pragma unroll 8
        for (int h = 0; h < H_DIM; h += 4) {
            float d0 = f[h]     - q[h];
            float d1 = f[h + 1] - q[h + 1];
            float d2 = f[h + 2] - q[h + 2];
            float d3 = f[h + 3] - q[h + 3];
            s0 = fmaf(d0, d0, s0);
            s1 = fmaf(d1, d1, s1);
            s2 = fmaf(d2, d2, s2);
            s3 = fmaf(d3, d3, s3);
        }
        sim[r][c] = sqrtf((s0 + s1) + (s2 + s3));
    }
    __syncthreads();
    if (t < TOPK) {
        float m = sim[t][0];
#pragma unroll
        for (int c = 1; c < C_DIM; c++) m = fmaxf(m, sim[t][c]);
        rowmax[t] = m;
    }
    __syncthreads();
    if (t < C_DIM) {
        float s = 0.f;
#pragma unroll
        for (int r = 0; r < TOPK; r++) s += sim[r][t] / rowmax[r];
        coding[t] = s / (float)TOPK;
    }
    __syncthreads();
    if (t < K_DIM) {
        float h = brho[t];
#pragma unroll
        for (int c = 0; c < C_DIM; c++) h = fmaf(coding[c], Wrho[c * K_DIM + t], h);
        hidden[t] = fmaxf(h, 0.f);
    }
    __syncthreads();
    if (t < 2) {
        float l = bc[t];
#pragma unroll
        for (int k = 0; k < K_DIM; k++) l = fmaf(hidden[k], Wc[k * 2 + t], l);
        logits[t] = l;
    }
    __syncthreads();
    if (t == 0) {
        float l0 = logits[0], l1 = logits[1];
        float m  = fmaxf(l0, l1);
        float e0 = expf(l0 - m), e1 = expf(l1 - m);
        float inv = 1.f / (e0 + e1);
        float p0 = e0 * inv, p1 = e1 * inv;

        float vals[5 + C_DIM];
        vals[0] = l0; vals[1] = l1;
        vals[2] = p0; vals[3] = p1;
        vals[4] = (p1 > p0) ? 1.f : 0.f;
#pragma unroll
        for (int c = 0; c < C_DIM; c++) vals[5 + c] = coding[c];

        int n = out_size < (5 + C_DIM) ? out_size : (5 + C_DIM);
        for (int i = 0; i < n; i++) out[i] = vals[i];
    }
}

// ---------------- host launcher ----------------
extern "C" void kernel_launch(void* const* d_in, const int* in_sizes, int n_in,
                              void* d_out, int out_size) {
    const float* x     = (const float*)d_in[0];
    const float* proto = (const float*)d_in[1];
    const float* W3    = (const float*)d_in[2];
    const float* W2    = (const float*)d_in[4];
    const float* b2    = (const float*)d_in[5];
    const float* Wrho  = (const float*)d_in[6];
    const float* brho  = (const float*)d_in[7];
    const float* Wc    = (const float*)d_in[8];
    const float* bc    = (const float*)d_in[9];
    float* out = (float*)d_out;

    int N = in_sizes[0] / F_DIM;
    if (N > N_MAX) N = N_MAX;
    int nb2   = (N + 1023) / 1024;               // total k2a chunks (<= 64)
    int nb2_1 = nb2 / 2;                         // first-half chunks
    int half  = nb2_1 * 1024;                    // first-half row count (1024-aligned)
    int nb2_2 = nb2 - nb2_1;

    static cudaStream_t s_side = nullptr, s_topk = nullptr;
    static cudaEvent_t  ev_fork = nullptr, ev_join = nullptr, ev_h1 = nullptr, ev_c1 = nullptr;
    static int k4_smem = R_TOT * PADW * (int)sizeof(float);   // ~76 KB
    if (s_side == nullptr) {
        cudaStreamCreateWithFlags(&s_side, cudaStreamNonBlocking);
        cudaStreamCreateWithFlags(&s_topk, cudaStreamNonBlocking);
        cudaEventCreateWithFlags(&ev_fork, cudaEventDisableTiming);
        cudaEventCreateWithFlags(&ev_join, cudaEventDisableTiming);
        cudaEventCreateWithFlags(&ev_h1,   cudaEventDisableTiming);
        cudaEventCreateWithFlags(&ev_c1,   cudaEventDisableTiming);
        cudaFuncSetAttribute(k4_head, cudaFuncAttributeMaxDynamicSharedMemorySize, k4_smem);
    }

    // fork: prototype embedding independent of top-k (runs beside k1)
    cudaEventRecord(ev_fork, 0);
    cudaStreamWaitEvent(s_side, ev_fork, 0);
    dim3 gp(RGP, KCHP);
    k3a_p<<<gp, 256, 0, s_side>>>(proto, W2);
    k3b_p<<<C_DIM, 256, 0, s_side>>>(b2);
    cudaEventRecord(ev_join, s_side);

    // k1 first half, then overlap its k2a with k1 second half
    int rows1 = half;
    int rows2 = N - half;
    k1_scores<<<(rows1 + ROWS_PB - 1) / ROWS_PB, 1024>>>(x, W3, 0, N);
    cudaEventRecord(ev_h1, 0);
    cudaStreamWaitEvent(s_topk, ev_h1, 0);
    if (nb2_1 > 0) k2a_topk<<<nb2_1, 1024, 0, s_topk>>>(0, 0, N);
    cudaEventRecord(ev_c1, s_topk);

    if (rows2 > 0) k1_scores<<<(rows2 + ROWS_PB - 1) / ROWS_PB, 1024>>>(x, W3, half, N);
    if (nb2_2 > 0) k2a_topk<<<nb2_2, 1024>>>(half, nb2_1, N);

    cudaStreamWaitEvent(0, ev_c1, 0);
    k2b_topk<<<1, 640>>>(nb2 * TOPK);

    dim3 gf(1, KCHF);
    k3a_f<<<gf, 256>>>(x, W2);
    k3b_f<<<TOPK, 256>>>(b2);

    cudaStreamWaitEvent(0, ev_join, 0);
    k4_head<<<1, 640, k4_smem>>>(Wrho, brho, Wc, bc, out, out_size);
}

// round 10
// speedup vs baseline: 1.1341x; 1.1341x over previous
#include <cuda_runtime.h>
#include <math.h>
#include <float.h>

// ---------------- problem constants ----------------
#define F_DIM 2048
#define H_DIM 256
#define C_DIM 64
#define K_DIM 16
#define TOPK  10
#define N_MAX 65536
#define EPS   1e-6f
#define R_TOT (TOPK + C_DIM)     // 74 embedding rows
#define PADW  257                // padded row width for k4 smem

#define NB2_MAX ((N_MAX + 1023) / 1024)   // k2a blocks (64)

// f-embedding chunking: 10 rows share W2 loads, 64 K-chunks of 32
#define KCHF  64
#define KCSZF (F_DIM / KCHF)     // 32
// proto-embedding chunking: 8 rows/group, 32 K-chunks of 64
#define RGP   8
#define KCHP  32
#define KCSZP (F_DIM / KCHP)     // 64

// ---------------- device scratch ----------------
__device__ unsigned long long g_keys[N_MAX];
__device__ unsigned long long g_cand[NB2_MAX * TOPK];
__device__ int   g_topidx[TOPK];
__device__ float g_part_f[TOPK * KCHF * H_DIM];
__device__ float g_part_p[C_DIM * KCHP * H_DIM];
__device__ float g_fp[R_TOT * H_DIM];   // rows 0..9 = f, 10..73 = p

// ---------------- key packing: larger key = better (higher score, then lower idx) ----------------
__device__ __forceinline__ unsigned long long make_key(float v, int idx) {
    unsigned int u = __float_as_uint(v);
    u = (u & 0x80000000u) ? ~u : (u | 0x80000000u);     // order-preserving float->uint
    return ((unsigned long long)u << 32) | (unsigned long long)(0x7fffffffu - (unsigned)idx);
}
__device__ __forceinline__ int key_idx(unsigned long long k) {
    return (int)(0x7fffffffu - (unsigned)(k & 0xffffffffu));
}

// warp bitonic sort of 32 u64 keys (descending; lane 0 ends with max)
__device__ __forceinline__ unsigned long long bitonic32(unsigned long long v, int lane) {
#pragma unroll
    for (int k = 2; k <= 32; k <<= 1) {
#pragma unroll
        for (int j = k >> 1; j > 0; j >>= 1) {
            unsigned long long o = __shfl_xor_sync(0xffffffffu, v, j);
            bool keepMax = (((lane & k) == 0) == ((lane & j) == 0));
            unsigned long long mx = v > o ? v : o;
            unsigned long long mn = v > o ? o : v;
            v = keepMax ? mx : mn;
        }
    }
    return v;
}

// warp-wide top-10 extraction over per-lane sorted lists (desc, 0-padded)
template <int L>
__device__ __forceinline__ void warp_top10(unsigned long long* arr, unsigned long long* out) {
#pragma unroll
    for (int it = 0; it < TOPK; it++) {
        unsigned long long m = arr[0];
#pragma unroll
        for (int off = 16; off; off >>= 1) {
            unsigned long long o = __shfl_xor_sync(0xffffffffu, m, off);
            if (o > m) m = o;
        }
        out[it] = m;
        if (arr[0] == m) {
#pragma unroll
            for (int i = 0; i < L - 1; i++) arr[i] = arr[i + 1];
            arr[L - 1] = 0ULL;
        }
    }
}

// ---------------- K1: keys[row] = pack(x[row] . w_diff, row) ----------------
// R6-proven shape: 512 threads = 16 warps, 1 row/warp, __ldcs streaming, single launch.
__global__ void __launch_bounds__(512) k1_scores(const float* __restrict__ x,
                                                 const float* __restrict__ W3,
                                                 int N) {
    __shared__ float ws[F_DIM];
    int tid = threadIdx.x;
    // stage w_diff = W3[:,1]-W3[:,0]: each thread 2 float4 of W3 -> 4 diffs
    const float4* w34 = reinterpret_cast<const float4*>(W3);   // 1024 float4
    float4 a = w34[2 * tid];
    float4 b = w34[2 * tid + 1];
    ws[4 * tid + 0] = a.y - a.x;
    ws[4 * tid + 1] = a.w - a.z;
    ws[4 * tid + 2] = b.y - b.x;
    ws[4 * tid + 3] = b.w - b.z;
    __syncthreads();

    int warp = tid >> 5;
    int lane = tid & 31;
    int row  = blockIdx.x * 16 + warp;
    if (row >= N) return;

    const float4* ws4 = reinterpret_cast<const float4*>(ws);
    const float4* xr  = reinterpret_cast<const float4*>(x + (size_t)row * F_DIM);
    float acc = 0.f;
#pragma unroll
    for (int it = 0; it < 16; it++) {
        float4 xv = __ldcs(&xr[lane + it * 32]);
        float4 wv = ws4[lane + it * 32];
        acc = fmaf(xv.x, wv.x, acc);
        acc = fmaf(xv.y, wv.y, acc);
        acc = fmaf(xv.z, wv.z, acc);
        acc = fmaf(xv.w, wv.w, acc);
    }
#pragma unroll
    for (int o = 16; o; o >>= 1) acc += __shfl_down_sync(0xffffffffu, acc, o);
    if (lane == 0) g_keys[row] = make_key(acc, row);
}

// ---------------- K2a: per-1024-chunk top-10 via warp bitonic ----------------
__global__ void __launch_bounds__(1024) k2a_topk(int N) {
    __shared__ unsigned long long w_sm[32 * TOPK];
    int tid  = threadIdx.x;
    int warp = tid >> 5;
    int lane = tid & 31;
    int idx  = blockIdx.x * 1024 + tid;

    unsigned long long key = (idx < N) ? g_keys[idx] : 0ULL;
    key = bitonic32(key, lane);
    if (lane < TOPK) w_sm[warp * TOPK + lane] = key;
    __syncthreads();

    if (warp == 0) {
        unsigned long long lst[TOPK];
#pragma unroll
        for (int j = 0; j < TOPK; j++) lst[j] = w_sm[lane * TOPK + j];
        unsigned long long out[TOPK];
        warp_top10<TOPK>(lst, out);
        if (lane == 0) {
#pragma unroll
            for (int j = 0; j < TOPK; j++) g_cand[(size_t)blockIdx.x * TOPK + j] = out[j];
        }
    }
}

// ---------------- K2b: merge <=640 candidates -> global top-10 ----------------
__global__ void __launch_bounds__(640) k2b_topk(int nc) {
    __shared__ unsigned long long w_sm[20 * TOPK];
    int tid  = threadIdx.x;
    int warp = tid >> 5;
    int lane = tid & 31;

    unsigned long long key = (tid < nc) ? g_cand[tid] : 0ULL;
    key = bitonic32(key, lane);
    if (lane < TOPK) w_sm[warp * TOPK + lane] = key;
    __syncthreads();

    if (warp == 0) {
        unsigned long long lst[TOPK];
#pragma unroll
        for (int j = 0; j < TOPK; j++) lst[j] = (lane < 20) ? w_sm[lane * TOPK + j] : 0ULL;
        unsigned long long out[TOPK];
        warp_top10<TOPK>(lst, out);
        if (lane == 0) {
#pragma unroll
            for (int j = 0; j < TOPK; j++) g_topidx[j] = key_idx(out[j]);
        }
    }
}

// ---------------- K3 (f rows): 10 gathered rows @ W2, grid (1, KCHF) ----------------
__global__ void __launch_bounds__(256) k3a_f(const float* __restrict__ x,
                                             const float* __restrict__ W2) {
    __shared__ float xs[TOPK][KCSZF];
    int t  = threadIdx.x;
    int kc = blockIdx.y;
    int kbase = kc * KCSZF;

    for (int i = t; i < TOPK * KCSZF; i += 256) {
        int r = i / KCSZF, c = i % KCSZF;
        xs[r][c] = x[(size_t)g_topidx[r] * F_DIM + kbase + c];
    }
    __syncthreads();

    float acc[TOPK];
#pragma unroll
    for (int i = 0; i < TOPK; i++) acc[i] = 0.f;

#pragma unroll
    for (int k0 = 0; k0 < KCSZF; k0 += 8) {
        float w[8];
#pragma unroll
        for (int u = 0; u < 8; u++)
            w[u] = W2[(size_t)(kbase + k0 + u) * H_DIM + t];
#pragma unroll
        for (int u = 0; u < 8; u++)
#pragma unroll
            for (int i = 0; i < TOPK; i++)
                acc[i] = fmaf(xs[i][k0 + u], w[u], acc[i]);
    }

#pragma unroll
    for (int i = 0; i < TOPK; i++)
        g_part_f[((size_t)i * KCHF + kc) * H_DIM + t] = acc[i];
}

__global__ void __launch_bounds__(256) k3b_f(const float* __restrict__ b2) {
    int r = blockIdx.x;
    int t = threadIdx.x;
    float s = b2[t];
#pragma unroll 8
    for (int c = 0; c < KCHF; c++) s += g_part_f[((size_t)r * KCHF + c) * H_DIM + t];
    g_fp[r * H_DIM + t] = s;
}

// ---------------- K3 (proto rows): side stream ----------------
__global__ void __launch_bounds__(256) k3a_p(const float* __restrict__ proto,
                                             const float* __restrict__ W2) {
    __shared__ float xs[RGP][KCSZP];
    int t  = threadIdx.x;
    int rg = blockIdx.x;
    int kc = blockIdx.y;
    int kbase = kc * KCSZP;

    for (int i = t; i < RGP * KCSZP; i += 256) {
        int r = i >> 6, c = i & 63;
        xs[r][c] = proto[(size_t)(rg * RGP + r) * F_DIM + kbase + c];
    }
    __syncthreads();

    float acc[RGP];
#pragma unroll
    for (int i = 0; i < RGP; i++) acc[i] = 0.f;

    for (int k0 = 0; k0 < KCSZP; k0 += 8) {
        float w[8];
#pragma unroll
        for (int u = 0; u < 8; u++)
            w[u] = W2[(size_t)(kbase + k0 + u) * H_DIM + t];
#pragma unroll
        for (int u = 0; u < 8; u++)
#pragma unroll
            for (int i = 0; i < RGP; i++)
                acc[i] = fmaf(xs[i][k0 + u], w[u], acc[i]);
    }

#pragma unroll
    for (int i = 0; i < RGP; i++)
        g_part_p[((size_t)(rg * RGP + i) * KCHP + kc) * H_DIM + t] = acc[i];
}

__global__ void __launch_bounds__(256) k3b_p(const float* __restrict__ b2) {
    int r = blockIdx.x;
    int t = threadIdx.x;
    float s = b2[t];
#pragma unroll 8
    for (int c = 0; c < KCHP; c++) s += g_part_p[((size_t)r * KCHP + c) * H_DIM + t];
    g_fp[(TOPK + r) * H_DIM + t] = s;
}

// ---------------- K4: similarity + normalize + mean + head ----------------
__global__ void __launch_bounds__(640) k4_head(const float* __restrict__ Wrho,
                                               const float* __restrict__ brho,
                                               const float* __restrict__ Wc,
                                               const float* __restrict__ bc,
                                               float* __restrict__ out,
                                               int out_size) {
    extern __shared__ float rows[];          // R_TOT * PADW floats
    __shared__ float sim[TOPK][C_DIM];
    __shared__ float rowmax[TOPK];
    __shared__ float coding[C_DIM];
    __shared__ float hidden[K_DIM];
    __shared__ float logits[2];
    int t = threadIdx.x;

    for (int i = t; i < R_TOT * H_DIM; i += 640) {
        int r = i >> 8;
        int h = i & 255;
        float v = g_fp[i];
        if (r >= TOPK) v -= EPS;             // fold +EPS into prototype rows
        rows[r * PADW + h] = v;
    }
    __syncthreads();

    {
        int r = t / C_DIM;
        int c = t % C_DIM;
        const float* f = rows + r * PADW;
        const float* q = rows + (TOPK + c) * PADW;
        float s0 = 0.f, s1 = 0.f, s2 = 0.f, s3 = 0.f;
#pragma unroll 8
        for (int h = 0; h < H_DIM; h += 4) {
            float d0 = f[h]     - q[h];
            float d1 = f[h + 1] - q[h + 1];
            float d2 = f[h + 2] - q[h + 2];
            float d3 = f[h + 3] - q[h + 3];
            s0 = fmaf(d0, d0, s0);
            s1 = fmaf(d1, d1, s1);
            s2 = fmaf(d2, d2, s2);
            s3 = fmaf(d3, d3, s3);
        }
        sim[r][c] = sqrtf((s0 + s1) + (s2 + s3));
    }
    __syncthreads();
    if (t < TOPK) {
        float m = sim[t][0];
#pragma unroll
        for (int c = 1; c < C_DIM; c++) m = fmaxf(m, sim[t][c]);
        rowmax[t] = m;
    }
    __syncthreads();
    if (t < C_DIM) {
        float s = 0.f;
#pragma unroll
        for (int r = 0; r < TOPK; r++) s += sim[r][t] / rowmax[r];
        coding[t] = s / (float)TOPK;
    }
    __syncthreads();
    if (t < K_DIM) {
        float h = brho[t];
#pragma unroll
        for (int c = 0; c < C_DIM; c++) h = fmaf(coding[c], Wrho[c * K_DIM + t], h);
        hidden[t] = fmaxf(h, 0.f);
    }
    __syncthreads();
    if (t < 2) {
        float l = bc[t];
#pragma unroll
        for (int k = 0; k < K_DIM; k++) l = fmaf(hidden[k], Wc[k * 2 + t], l);
        logits[t] = l;
    }
    __syncthreads();
    if (t == 0) {
        float l0 = logits[0], l1 = logits[1];
        float m  = fmaxf(l0, l1);
        float e0 = expf(l0 - m), e1 = expf(l1 - m);
        float inv = 1.f / (e0 + e1);
        float p0 = e0 * inv, p1 = e1 * inv;

        float vals[5 + C_DIM];
        vals[0] = l0; vals[1] = l1;
        vals[2] = p0; vals[3] = p1;
        vals[4] = (p1 > p0) ? 1.f : 0.f;
#pragma unroll
        for (int c = 0; c < C_DIM; c++) vals[5 + c] = coding[c];

        int n = out_size < (5 + C_DIM) ? out_size : (5 + C_DIM);
        for (int i = 0; i < n; i++) out[i] = vals[i];
    }
}

// ---------------- host launcher ----------------
extern "C" void kernel_launch(void* const* d_in, const int* in_sizes, int n_in,
                              void* d_out, int out_size) {
    const float* x     = (const float*)d_in[0];
    const float* proto = (const float*)d_in[1];
    const float* W3    = (const float*)d_in[2];
    const float* W2    = (const float*)d_in[4];
    const float* b2    = (const float*)d_in[5];
    const float* Wrho  = (const float*)d_in[6];
    const float* brho  = (const float*)d_in[7];
    const float* Wc    = (const float*)d_in[8];
    const float* bc    = (const float*)d_in[9];
    float* out = (float*)d_out;

    int N = in_sizes[0] / F_DIM;
    if (N > N_MAX) N = N_MAX;
    int nb2 = (N + 1023) / 1024;               // k2a blocks (<= 64)

    static cudaStream_t s_side = nullptr;
    static cudaEvent_t  ev_fork = nullptr, ev_join = nullptr;
    static int k4_smem = R_TOT * PADW * (int)sizeof(float);   // ~76 KB
    if (s_side == nullptr) {
        cudaStreamCreateWithFlags(&s_side, cudaStreamNonBlocking);
        cudaEventCreateWithFlags(&ev_fork, cudaEventDisableTiming);
        cudaEventCreateWithFlags(&ev_join, cudaEventDisableTiming);
        cudaFuncSetAttribute(k4_head, cudaFuncAttributeMaxDynamicSharedMemorySize, k4_smem);
    }

    // fork: prototype embedding independent of top-k (runs beside k1)
    cudaEventRecord(ev_fork, 0);
    cudaStreamWaitEvent(s_side, ev_fork, 0);
    dim3 gp(RGP, KCHP);
    k3a_p<<<gp, 256, 0, s_side>>>(proto, W2);
    k3b_p<<<C_DIM, 256, 0, s_side>>>(b2);
    cudaEventRecord(ev_join, s_side);

    // main critical path
    k1_scores<<<(N + 15) / 16, 512>>>(x, W3, N);
    k2a_topk<<<nb2, 1024>>>(N);
    k2b_topk<<<1, 640>>>(nb2 * TOPK);
    dim3 gf(1, KCHF);
    k3a_f<<<gf, 256>>>(x, W2);
    k3b_f<<<TOPK, 256>>>(b2);

    cudaStreamWaitEvent(0, ev_join, 0);
    k4_head<<<1, 640, k4_smem>>>(Wrho, brho, Wc, bc, out, out_size);
}